// round 11
// baseline (speedup 1.0000x reference)
#include <cuda_runtime.h>
#include <cuda_bf16.h>

// RelativePositionEncoding (AF3-style), GB300 sm_103a — R9
//
// out[i,j,:] = W_pos[dr] + W_tok[dt] + same_ent*w_ent + W_chain[dk]
// Fusions (proven since R2):
//   F[0..66)  = W_pos[r]  + W_tok[65]   (d_residue branch, !same_cr)
//   F[66..132)= W_pos[32] + W_tok[t]    (d_token branch,    same_cr)
//   C[e*6+k]  = W_chain[k] + e*w_ent
//
// R9 = R8 (persistent 456x512, half-row units, atomic stealing, sequential
// stores) + predicated-LDS hot loop:
//   f==65 (diff chain) holds for ~7/8 of pairs. F[65] lives in registers;
//   the t4[f] LDS.128 issues only under @p (f!=65) — predicated-off memory
//   ops consume no smem wavefront. Avg LDS/pair 2.0 -> ~1.13, store order
//   unchanged. Clean test of LSU/L1-contention vs pure-DRAM-write ceiling.

#define N_TOK 1536
#define CZ 128
#define QJ 768
#define N_UNITS (N_TOK * 2)
#define N_CTAS 456
#define NTHREADS 512
#define TBL_FLOATS (144 * CZ)
#define SMEM_BYTES (TBL_FLOATS * 4 + QJ * 2 + 16)

__device__ int g_ctr;

__global__ void reset_ctr() { g_ctr = 0; }

__global__ __launch_bounds__(NTHREADS, 3)
void relpos_kernel(const int* __restrict__ asym,
                   const int* __restrict__ resi,
                   const int* __restrict__ enti,
                   const int* __restrict__ toki,
                   const int* __restrict__ symi,
                   const float* __restrict__ W,
                   float* __restrict__ out)
{
    extern __shared__ float sW[];                              // [144][128]
    unsigned short* sIdx = (unsigned short*)(sW + TBL_FLOATS); // [QJ]
    int* sU = (int*)(sIdx + QJ);

    const int tid = threadIdx.x;

    // ---- One-time table build (per CTA) ----
    // W rows: [0,66)=pos, [66,132)=tok, 132=w_ent, [133,139)=chain
    #pragma unroll 4
    for (int idx = tid; idx < 132 * CZ; idx += NTHREADS) {
        const int row = idx >> 7;
        const int c   = idx & (CZ - 1);
        float v;
        if (row < 66) v = W[row * CZ + c] + W[131 * CZ + c];   // pos[row]+tok[65]
        else          v = W[32  * CZ + c] + W[row * CZ + c];   // pos[32]+tok[row-66]
        sW[idx] = v;
    }
    for (int idx = tid; idx < 12 * CZ; idx += NTHREADS) {
        const int row = idx >> 7;
        const int c   = idx & (CZ - 1);
        const int e   = row / 6;
        const int k   = row % 6;
        float v = W[(133 + k) * CZ + c];
        if (e) v += W[132 * CZ + c];
        sW[132 * CZ + idx] = v;
    }

    if (tid == 0) sU[0] = atomicAdd(&g_ctr, 1);
    __syncthreads();
    int u = sU[0];

    const int lane = tid & 31;
    const int warp = tid >> 5;
    const float4* __restrict__ t4 = reinterpret_cast<const float4*>(sW);
    const float4* __restrict__ c4 = t4 + 132 * 32;
    float4* __restrict__ out4 = reinterpret_cast<float4*>(out);

    // Register-cached diff-chain pos/tok row F[65].
    const float4 rF65 = t4[65 * 32 + lane];
    // smem byte address bases for predicated LDS.
    const unsigned t4_addr = (unsigned)__cvta_generic_to_shared(sW) + lane * 16u;

    while (u < N_UNITS) {
        const int i  = u >> 1;
        const int jb = (u & 1) * QJ;

        const int ai = __ldg(asym + i);
        const int ri = __ldg(resi + i);
        const int ei = __ldg(enti + i);
        const int ti = __ldg(toki + i);
        const int si = __ldg(symi + i);

        #pragma unroll 2
        for (int t = tid; t < QJ; t += NTHREADS) {
            const int j  = jb + t;
            const int aj = __ldg(asym + j);
            const int rj = __ldg(resi + j);
            const int ej = __ldg(enti + j);
            const int tj = __ldg(toki + j);
            const int sj = __ldg(symi + j);

            const bool sc  = (ai == aj);
            const bool scr = sc && (ri == rj);
            int f;
            if (scr)      f = 66 + min(max(ti - tj + 32, 0), 64);
            else if (sc)  f = min(max(ri - rj + 32, 0), 64);
            else          f = 65;
            const bool se = (ei == ej);
            const int  dk = se ? min(max(si - sj + 2, 0), 4) : 5;
            const int  dc = (se ? 6 : 0) + dk;
            sIdx[t] = (unsigned short)(f | (dc << 8));
        }
        if (tid == 0) sU[0] = atomicAdd(&g_ctr, 1);
        __syncthreads();

        float4* __restrict__ o = out4 + ((size_t)i * N_TOK + jb) * 32 + lane;

        #pragma unroll 2
        for (int j = warp * 2; j < QJ; j += 32) {
            const unsigned p0 = sIdx[j];
            const unsigned p1 = sIdx[j + 1];
            const unsigned f0 = p0 & 0xFFu, d0 = p0 >> 8;
            const unsigned f1 = p1 & 0xFFu, d1 = p1 >> 8;

            // chain row: always 1 LDS.128 (12-row table, conflict-free)
            const float4 b0 = c4[d0 * 32 + lane];
            const float4 b1 = c4[d1 * 32 + lane];

            // pos/tok row: register F[65] unless f!=65 (predicated LDS.128)
            float4 a0 = rF65, a1 = rF65;
            asm volatile(
                "{\n\t.reg .pred p;\n\t"
                "setp.ne.u32 p, %4, 65;\n\t"
                "@p ld.shared.v4.f32 {%0,%1,%2,%3}, [%5];\n\t}"
                : "+f"(a0.x), "+f"(a0.y), "+f"(a0.z), "+f"(a0.w)
                : "r"(f0), "r"(t4_addr + f0 * 512u));
            asm volatile(
                "{\n\t.reg .pred p;\n\t"
                "setp.ne.u32 p, %4, 65;\n\t"
                "@p ld.shared.v4.f32 {%0,%1,%2,%3}, [%5];\n\t}"
                : "+f"(a1.x), "+f"(a1.y), "+f"(a1.z), "+f"(a1.w)
                : "r"(f1), "r"(t4_addr + f1 * 512u));

            float4 r0, r1;
            r0.x = a0.x + b0.x; r0.y = a0.y + b0.y; r0.z = a0.z + b0.z; r0.w = a0.w + b0.w;
            r1.x = a1.x + b1.x; r1.y = a1.y + b1.y; r1.z = a1.z + b1.z; r1.w = a1.w + b1.w;

            __stcs(&o[(size_t)j * 32],       r0);
            __stcs(&o[(size_t)(j + 1) * 32], r1);
        }

        const int nu = sU[0];
        __syncthreads();
        u = nu;
    }
}

extern "C" void kernel_launch(void* const* d_in, const int* in_sizes, int n_in,
                              void* d_out, int out_size)
{
    const int*   asym = (const int*)d_in[0];
    const int*   resi = (const int*)d_in[1];
    const int*   enti = (const int*)d_in[2];
    const int*   toki = (const int*)d_in[3];
    const int*   symi = (const int*)d_in[4];
    const float* W    = (const float*)d_in[5];
    float*       out  = (float*)d_out;

    cudaFuncSetAttribute(relpos_kernel,
                         cudaFuncAttributeMaxDynamicSharedMemorySize, SMEM_BYTES);

    reset_ctr<<<1, 1>>>();
    relpos_kernel<<<N_CTAS, NTHREADS, SMEM_BYTES>>>(asym, resi, enti, toki, symi, W, out);
}

// round 12
// speedup vs baseline: 1.4127x; 1.4127x over previous
#include <cuda_runtime.h>
#include <cuda_bf16.h>

// RelativePositionEncoding (AF3-style), GB300 sm_103a — R10
//
// out[i,j,:] = W_pos[dr] + W_tok[dt] + same_ent*w_ent + W_chain[dk]
// Fusions (proven since R2):
//   F[0..66)  = W_pos[r]  + W_tok[65]   (d_residue branch, !same_cr)
//   F[66..132)= W_pos[32] + W_tok[t]    (d_token branch,    same_cr)
//   C[e*6+k]  = W_chain[k] + e*w_ent
//
// R10 = R8 (persistent 456x512, half-row units, atomic stealing, sequential
// stores; best known 175.1us, 6.45 TB/s = LTS chip cap) with hot-loop
// unroll x4: each warp emits 4 consecutive j's (2KB contiguous) per
// iteration — 4 independent LDS pairs + 4 STG.128 in flight, half the loop
// overhead. Store order and total traffic unchanged.

#define N_TOK 1536
#define CZ 128
#define QJ 768                          // j's per unit (half row)
#define N_UNITS (N_TOK * 2)             // 3072
#define N_CTAS 456                      // 152 SMs * 3
#define NTHREADS 512
#define TBL_FLOATS (144 * CZ)
#define SMEM_BYTES (TBL_FLOATS * 4 + QJ * 2 + 16)

__device__ int g_ctr;

__global__ void reset_ctr() { g_ctr = 0; }

__global__ __launch_bounds__(NTHREADS, 3)
void relpos_kernel(const int* __restrict__ asym,
                   const int* __restrict__ resi,
                   const int* __restrict__ enti,
                   const int* __restrict__ toki,
                   const int* __restrict__ symi,
                   const float* __restrict__ W,
                   float* __restrict__ out)
{
    extern __shared__ float sW[];                              // [144][128]
    unsigned short* sIdx = (unsigned short*)(sW + TBL_FLOATS); // [QJ]
    int* sU = (int*)(sIdx + QJ);                               // stolen unit

    const int tid = threadIdx.x;

    // ---- One-time table build (per CTA) ----
    // W rows: [0,66)=pos, [66,132)=tok, 132=w_ent, [133,139)=chain
    #pragma unroll 4
    for (int idx = tid; idx < 132 * CZ; idx += NTHREADS) {
        const int row = idx >> 7;
        const int c   = idx & (CZ - 1);
        float v;
        if (row < 66) v = W[row * CZ + c] + W[131 * CZ + c];   // pos[row]+tok[65]
        else          v = W[32  * CZ + c] + W[row * CZ + c];   // pos[32]+tok[row-66]
        sW[idx] = v;
    }
    for (int idx = tid; idx < 12 * CZ; idx += NTHREADS) {
        const int row = idx >> 7;
        const int c   = idx & (CZ - 1);
        const int e   = row / 6;
        const int k   = row % 6;
        float v = W[(133 + k) * CZ + c];
        if (e) v += W[132 * CZ + c];
        sW[132 * CZ + idx] = v;
    }

    if (tid == 0) sU[0] = atomicAdd(&g_ctr, 1);
    __syncthreads();                    // table RAW + first unit visible
    int u = sU[0];

    const int lane = tid & 31;
    const int warp = tid >> 5;
    const float4* __restrict__ t4 = reinterpret_cast<const float4*>(sW);
    const float4* __restrict__ c4 = t4 + 132 * 32;
    float4* __restrict__ out4 = reinterpret_cast<float4*>(out);

    while (u < N_UNITS) {
        const int i  = u >> 1;
        const int jb = (u & 1) * QJ;

        // ---- Stage packed indices for this unit (all threads) ----
        const int ai = __ldg(asym + i);
        const int ri = __ldg(resi + i);
        const int ei = __ldg(enti + i);
        const int ti = __ldg(toki + i);
        const int si = __ldg(symi + i);

        #pragma unroll 2
        for (int t = tid; t < QJ; t += NTHREADS) {
            const int j  = jb + t;
            const int aj = __ldg(asym + j);
            const int rj = __ldg(resi + j);
            const int ej = __ldg(enti + j);
            const int tj = __ldg(toki + j);
            const int sj = __ldg(symi + j);

            const bool sc  = (ai == aj);
            const bool scr = sc && (ri == rj);
            int f;
            if (scr)      f = 66 + min(max(ti - tj + 32, 0), 64);
            else if (sc)  f = min(max(ri - rj + 32, 0), 64);
            else          f = 65;
            const bool se = (ei == ej);
            const int  dk = se ? min(max(si - sj + 2, 0), 4) : 5;
            const int  dc = (se ? 6 : 0) + dk;
            sIdx[t] = (unsigned short)(f | (dc << 8));
        }
        if (tid == 0) sU[0] = atomicAdd(&g_ctr, 1);   // prefetch next unit
        __syncthreads();                               // RAW: sIdx + sU ready

        // ---- Hot loop: 16 warps, 4 consecutive j's per warp-iteration ----
        float4* __restrict__ o = out4 + ((size_t)i * N_TOK + jb) * 32 + lane;

        for (int j = warp * 4; j < QJ; j += 64) {
            const unsigned p0 = sIdx[j];
            const unsigned p1 = sIdx[j + 1];
            const unsigned p2 = sIdx[j + 2];
            const unsigned p3 = sIdx[j + 3];

            const float4 a0 = t4[(p0 & 0xFFu) * 32 + lane];
            const float4 b0 = c4[(p0 >> 8)    * 32 + lane];
            const float4 a1 = t4[(p1 & 0xFFu) * 32 + lane];
            const float4 b1 = c4[(p1 >> 8)    * 32 + lane];
            const float4 a2 = t4[(p2 & 0xFFu) * 32 + lane];
            const float4 b2 = c4[(p2 >> 8)    * 32 + lane];
            const float4 a3 = t4[(p3 & 0xFFu) * 32 + lane];
            const float4 b3 = c4[(p3 >> 8)    * 32 + lane];

            float4 r0, r1, r2, r3;
            r0.x = a0.x + b0.x; r0.y = a0.y + b0.y; r0.z = a0.z + b0.z; r0.w = a0.w + b0.w;
            r1.x = a1.x + b1.x; r1.y = a1.y + b1.y; r1.z = a1.z + b1.z; r1.w = a1.w + b1.w;
            r2.x = a2.x + b2.x; r2.y = a2.y + b2.y; r2.z = a2.z + b2.z; r2.w = a2.w + b2.w;
            r3.x = a3.x + b3.x; r3.y = a3.y + b3.y; r3.z = a3.z + b3.z; r3.w = a3.w + b3.w;

            __stcs(&o[(size_t)j * 32],       r0);
            __stcs(&o[(size_t)(j + 1) * 32], r1);
            __stcs(&o[(size_t)(j + 2) * 32], r2);
            __stcs(&o[(size_t)(j + 3) * 32], r3);
        }

        const int nu = sU[0];
        __syncthreads();               // WAR: all reads of sIdx/sU done
        u = nu;
    }
}

extern "C" void kernel_launch(void* const* d_in, const int* in_sizes, int n_in,
                              void* d_out, int out_size)
{
    const int*   asym = (const int*)d_in[0];
    const int*   resi = (const int*)d_in[1];
    const int*   enti = (const int*)d_in[2];
    const int*   toki = (const int*)d_in[3];
    const int*   symi = (const int*)d_in[4];
    const float* W    = (const float*)d_in[5];
    float*       out  = (float*)d_out;

    cudaFuncSetAttribute(relpos_kernel,
                         cudaFuncAttributeMaxDynamicSharedMemorySize, SMEM_BYTES);

    reset_ctr<<<1, 1>>>();
    relpos_kernel<<<N_CTAS, NTHREADS, SMEM_BYTES>>>(asym, resi, enti, toki, symi, W, out);
}